// round 17
// baseline (speedup 1.0000x reference)
#include <cuda_runtime.h>
#include <cuda_bf16.h>
#include <cstdint>
#include <cstddef>

// ---------------------------------------------------------------------------
// TTLinear. Phase A: 3 big tf32 tensor-core GEMMs. Phase B: one persistent
// kernel, 128 steps, 4 barriers/step (was 8). R17: regions merged by weight
// version: P1 = h2(t-1) + a/h(t) (full-K, fused gelu, no partials);
// P2 = out(t-1) + dr(t); P3 = da (full-K fused); P4 = updates. All tiles are
// 4-stage cp.async pipelines (R16 machinery). g_part eliminated.
// ---------------------------------------------------------------------------

constexpr int T_  = 128;
constexpr int NB  = 256;
constexpr int DD  = 1024;
constexpr int HH  = 1024;
constexpr int H4  = 256;
constexpr int NH  = NB * HH;    // 262144
constexpr int MN  = NB * H4;    // 65536
constexpr float LR = 1e-3f;
constexpr float C2 = 2.0f / (float)(NB * HH);

constexpr int SMM = 20;         // m-major smem row stride (16 k + 4 pad)
constexpr int SKM = 72;         // k-major smem row stride (64 + 8 pad)
constexpr int STG_FL = 2560;    // floats per stage (A at 0, B at 1280)

// ------------------------- device scratch ----------------------------------
__device__ float g_Z[(size_t)T_ * NH];
__device__ float g_Y[(size_t)T_ * NH];
__device__ float g_Q[(size_t)T_ * NH];
__device__ float g_W1[H4 * HH];
__device__ float g_b1[H4];
__device__ float g_W2[HH * H4];
__device__ float g_b2[HH];
__device__ float g_a[MN];
__device__ float g_h[MN];
__device__ float g_h2[MN];
__device__ float g_da[MN];
__device__ float g_dr[NB * HH];

__device__ __align__(128) unsigned g_cnt = 0;
__device__ __align__(128) unsigned g_gen = 0;

// ------------------------------ helpers ------------------------------------
__device__ __forceinline__ float gelu_f(float x) {
    return 0.5f * x * (1.0f + erff(x * 0.70710678118654752f));
}
__device__ __forceinline__ float gelu_grad(float x) {
    float cdf = 0.5f * (1.0f + erff(x * 0.70710678118654752f));
    float pdf = 0.3989422804014327f * expf(-0.5f * x * x);
    return cdf + x * pdf;
}
__device__ __forceinline__ float to_tf32(float x) {
    uint32_t u;
    asm("cvt.rna.tf32.f32 %0, %1;" : "=r"(u) : "f"(x));
    return __uint_as_float(u);
}
__device__ __forceinline__ void mma_tf32(float (&c)[4], const uint32_t (&a)[4],
                                         const uint32_t (&b)[2]) {
    asm volatile(
        "mma.sync.aligned.m16n8k8.row.col.f32.tf32.tf32.f32 "
        "{%0,%1,%2,%3}, {%4,%5,%6,%7}, {%8,%9}, {%0,%1,%2,%3};"
        : "+f"(c[0]), "+f"(c[1]), "+f"(c[2]), "+f"(c[3])
        : "r"(a[0]), "r"(a[1]), "r"(a[2]), "r"(a[3]), "r"(b[0]), "r"(b[1]));
}
__device__ __forceinline__ void cp16(unsigned dst, const void* src) {
    asm volatile("cp.async.cg.shared.global [%0], [%1], 16;" :: "r"(dst), "l"(src));
}
__device__ __forceinline__ void cp_commit() {
    asm volatile("cp.async.commit_group;");
}
template <int N>
__device__ __forceinline__ void cp_wait() {
    asm volatile("cp.async.wait_group %0;" :: "n"(N));
}

// Hot-spin grid barrier, bounded (sync bug -> wrong output, not a hang).
__device__ __forceinline__ void grid_sync(unsigned nb) {
    __syncthreads();
    if (threadIdx.x == 0) {
        unsigned gen = *(volatile unsigned*)&g_gen;
        __threadfence();
        if (atomicAdd(&g_cnt, 1) == nb - 1) {
            g_cnt = 0;
            __threadfence();
            atomicAdd(&g_gen, 1);
        } else {
            for (int spin = 0; spin < 1000000; spin++) {
                if (*(volatile unsigned*)&g_gen != gen) break;
            }
        }
        __threadfence();
    }
    __syncthreads();
}

// ---------------------------------------------------------------------------
// Phase A: C[M,N] = A[M,K] @ B[N,K]^T via tf32 mma.sync (unchanged, passing).
// ---------------------------------------------------------------------------
__global__ __launch_bounds__(256, 2) void gemm_nt_tf32(
    const float* __restrict__ A, const float* __restrict__ B,
    float* __restrict__ C, int M, int N, int K)
{
    __shared__ float As[2][16][136];
    __shared__ float Bs[2][16][136];
    const int m0 = blockIdx.x * 128, n0 = blockIdx.y * 128;
    const int tid = threadIdx.x;
    const int lrow = tid & 127, lc8 = (tid >> 7) * 8;
    const int w = tid >> 5, lane = tid & 31;
    const int wm = w >> 2, wn = w & 3;
    const int g = lane >> 2, q = lane & 3;

    float acc[4][4][4] = {};
    const float* Ag = A + (size_t)(m0 + lrow) * K + lc8;
    const float* Bg = B + (size_t)(n0 + lrow) * K + lc8;

    float4 ra0 = *(const float4*)(Ag);
    float4 ra1 = *(const float4*)(Ag + 4);
    float4 rb0 = *(const float4*)(Bg);
    float4 rb1 = *(const float4*)(Bg + 4);

    const int S = K / 16;
    for (int s = 0; s < S; s++) {
        const int buf = s & 1;
        {
            float* pa = &As[buf][lc8][lrow];
            pa[0*136] = to_tf32(ra0.x); pa[1*136] = to_tf32(ra0.y);
            pa[2*136] = to_tf32(ra0.z); pa[3*136] = to_tf32(ra0.w);
            pa[4*136] = to_tf32(ra1.x); pa[5*136] = to_tf32(ra1.y);
            pa[6*136] = to_tf32(ra1.z); pa[7*136] = to_tf32(ra1.w);
            float* pb = &Bs[buf][lc8][lrow];
            pb[0*136] = to_tf32(rb0.x); pb[1*136] = to_tf32(rb0.y);
            pb[2*136] = to_tf32(rb0.z); pb[3*136] = to_tf32(rb0.w);
            pb[4*136] = to_tf32(rb1.x); pb[5*136] = to_tf32(rb1.y);
            pb[6*136] = to_tf32(rb1.z); pb[7*136] = to_tf32(rb1.w);
        }
        if (s + 1 < S) {
            const float* a2 = Ag + (s + 1) * 16;
            const float* b2 = Bg + (s + 1) * 16;
            ra0 = *(const float4*)(a2);     ra1 = *(const float4*)(a2 + 4);
            rb0 = *(const float4*)(b2);     rb1 = *(const float4*)(b2 + 4);
        }
        __syncthreads();
#pragma unroll
        for (int kc = 0; kc < 16; kc += 8) {
            uint32_t af[4][4], bf[4][2];
#pragma unroll
            for (int mt = 0; mt < 4; mt++) {
                int r = wm * 64 + mt * 16 + g;
                af[mt][0] = __float_as_uint(As[buf][kc + q][r]);
                af[mt][1] = __float_as_uint(As[buf][kc + q][r + 8]);
                af[mt][2] = __float_as_uint(As[buf][kc + q + 4][r]);
                af[mt][3] = __float_as_uint(As[buf][kc + q + 4][r + 8]);
            }
#pragma unroll
            for (int nt = 0; nt < 4; nt++) {
                int c = wn * 32 + nt * 8 + g;
                bf[nt][0] = __float_as_uint(Bs[buf][kc + q][c]);
                bf[nt][1] = __float_as_uint(Bs[buf][kc + q + 4][c]);
            }
#pragma unroll
            for (int mt = 0; mt < 4; mt++)
#pragma unroll
                for (int nt = 0; nt < 4; nt++)
                    mma_tf32(acc[mt][nt], af[mt], bf[nt]);
        }
        __syncthreads();
    }
#pragma unroll
    for (int mt = 0; mt < 4; mt++)
#pragma unroll
        for (int nt = 0; nt < 4; nt++) {
            int r = m0 + wm * 64 + mt * 16 + g;
            int c = n0 + wn * 32 + nt * 8 + q * 2;
            *(float2*)&C[(size_t)r * N + c] =
                make_float2(acc[mt][nt][0], acc[mt][nt][1]);
            *(float2*)&C[(size_t)(r + 8) * N + c] =
                make_float2(acc[mt][nt][2], acc[mt][nt][3]);
        }
}

// ---------------------------------------------------------------------------
// cp.async slab issue (R16 machinery, unchanged).
// MODE 0 NT: A[m,k],B[n,k]; MODE 1 NN: A[m,k],B[k,n]; MODE 2 TN: A[k,m],B[k,n]
// ---------------------------------------------------------------------------
template <int MODE, int TM>
__device__ __forceinline__ void issue_slab(
    const float* __restrict__ A, const float* __restrict__ B, unsigned smu,
    int lda, int ldb, int m0, int n0, int k0, int st, int tid)
{
    unsigned sa = smu + (unsigned)(st * STG_FL) * 4u;
    unsigned sb = sa + 1280u * 4u;
    if (MODE == 2) {
        int k = tid >> 4, m4 = (tid & 15) * 4;
        cp16(sa + (unsigned)(k * SKM + m4) * 4u,
             A + (size_t)(k0 + k) * lda + m0 + m4);
    } else if (TM == 64) {
        int r = tid >> 2, c4 = (tid & 3) * 4;
        cp16(sa + (unsigned)(r * SMM + c4) * 4u,
             A + (size_t)(m0 + r) * lda + k0 + c4);
    } else {
        if (tid < 128) {
            int r = tid >> 2, c4 = (tid & 3) * 4;
            cp16(sa + (unsigned)(r * SMM + c4) * 4u,
                 A + (size_t)(m0 + r) * lda + k0 + c4);
        }
    }
    if (MODE == 0) {
        int r = tid >> 2, c4 = (tid & 3) * 4;
        cp16(sb + (unsigned)(r * SMM + c4) * 4u,
             B + (size_t)(n0 + r) * ldb + k0 + c4);
    } else {
        int k = tid >> 4, n4 = (tid & 15) * 4;
        cp16(sb + (unsigned)(k * SKM + n4) * 4u,
             B + (size_t)(k0 + k) * ldb + n0 + n4);
    }
    cp_commit();
}

// ---------------------------------------------------------------------------
// Phase B tile: TM x 64, tf32 mma, 4-stage cp.async pipeline (R16 machinery).
// SPLIT 0: plain tf32; 1: 3-mma split-tf32 (near-fp32 output path).
// ---------------------------------------------------------------------------
template <int MODE, int TM, int SPLIT>
__device__ __forceinline__ void tile_cp(
    const float* __restrict__ A, const float* __restrict__ B,
    float* sm, unsigned smu,
    int lda, int ldb, int m0, int n0, int kbeg, int kend,
    float (&acc)[TM / 32][2][4])
{
    const int tid = threadIdx.x;
    const int w = tid >> 5, lane = tid & 31;
    const int wm = w >> 2, wn = w & 3;
    const int g = lane >> 2, q = lane & 3;
    const int nslab = (kend - kbeg) >> 4;

#pragma unroll
    for (int s = 0; s < 3; s++)
        issue_slab<MODE, TM>(A, B, smu, lda, ldb, m0, n0, kbeg + s * 16, s, tid);

    for (int s = 0; s < nslab; s++) {
        const int st = s & 3;
        const int rem = nslab - s;
        if (rem > 2)      cp_wait<2>();
        else if (rem == 2) cp_wait<1>();
        else               cp_wait<0>();
        __syncthreads();
        if (s + 3 < nslab)
            issue_slab<MODE, TM>(A, B, smu, lda, ldb, m0, n0,
                                 kbeg + (s + 3) * 16, (s + 3) & 3, tid);
        const float* cA = sm + st * STG_FL;
        const float* cB = sm + st * STG_FL + 1280;
#pragma unroll
        for (int kc = 0; kc < 16; kc += 8) {
            float a0[TM / 32], a1[TM / 32], a2[TM / 32], a3[TM / 32];
#pragma unroll
            for (int mt = 0; mt < TM / 32; mt++) {
                int r = wm * (TM / 2) + mt * 16 + g;
                if (MODE == 2) {
                    a0[mt] = cA[(kc + q) * SKM + r];
                    a1[mt] = cA[(kc + q) * SKM + r + 8];
                    a2[mt] = cA[(kc + q + 4) * SKM + r];
                    a3[mt] = cA[(kc + q + 4) * SKM + r + 8];
                } else {
                    a0[mt] = cA[r * SMM + kc + q];
                    a1[mt] = cA[(r + 8) * SMM + kc + q];
                    a2[mt] = cA[r * SMM + kc + q + 4];
                    a3[mt] = cA[(r + 8) * SMM + kc + q + 4];
                }
            }
            float b0[2], b1[2];
#pragma unroll
            for (int nt = 0; nt < 2; nt++) {
                int c = wn * 16 + nt * 8 + g;
                if (MODE == 0) {
                    b0[nt] = cB[c * SMM + kc + q];
                    b1[nt] = cB[c * SMM + kc + q + 4];
                } else {
                    b0[nt] = cB[(kc + q) * SKM + c];
                    b1[nt] = cB[(kc + q + 4) * SKM + c];
                }
            }
            if (SPLIT == 0) {
#pragma unroll
                for (int mt = 0; mt < TM / 32; mt++) {
                    uint32_t af[4] = {__float_as_uint(a0[mt]), __float_as_uint(a1[mt]),
                                      __float_as_uint(a2[mt]), __float_as_uint(a3[mt])};
#pragma unroll
                    for (int nt = 0; nt < 2; nt++) {
                        uint32_t bf[2] = {__float_as_uint(b0[nt]), __float_as_uint(b1[nt])};
                        mma_tf32(acc[mt][nt], af, bf);
                    }
                }
            } else {
#pragma unroll
                for (int mt = 0; mt < TM / 32; mt++) {
                    float h0 = to_tf32(a0[mt]), h1 = to_tf32(a1[mt]);
                    float h2 = to_tf32(a2[mt]), h3 = to_tf32(a3[mt]);
                    uint32_t afh[4] = {__float_as_uint(h0), __float_as_uint(h1),
                                       __float_as_uint(h2), __float_as_uint(h3)};
                    uint32_t afl[4] = {__float_as_uint(to_tf32(a0[mt] - h0)),
                                       __float_as_uint(to_tf32(a1[mt] - h1)),
                                       __float_as_uint(to_tf32(a2[mt] - h2)),
                                       __float_as_uint(to_tf32(a3[mt] - h3))};
#pragma unroll
                    for (int nt = 0; nt < 2; nt++) {
                        float g0 = to_tf32(b0[nt]), g1 = to_tf32(b1[nt]);
                        uint32_t bfh[2] = {__float_as_uint(g0), __float_as_uint(g1)};
                        uint32_t bfl[2] = {__float_as_uint(to_tf32(b0[nt] - g0)),
                                           __float_as_uint(to_tf32(b1[nt] - g1))};
                        mma_tf32(acc[mt][nt], afh, bfh);
                        mma_tf32(acc[mt][nt], afl, bfh);
                        mma_tf32(acc[mt][nt], afh, bfl);
                    }
                }
            }
        }
    }
    __syncthreads();
}

// ---------------------------------------------------------------------------
// Persistent Phase B: 4 barriers per step.
//  P1: h2(i-1)=gelu(Q@W1) [split-tf32, full-K] + a,h(i)=gelu(Z@W1) [tf32,full-K]
//  P2: out(i-1)=Q+h2@W2^T+b2 [split-tf32, K=256] + dr(i) [tf32, K=256]
//  P3: da(i) = (dr@W2)*gelu'(a) [tf32, full-K, fused]
//  P4: weight + bias updates [tf32 TN, K=256]
// ---------------------------------------------------------------------------
__global__ __launch_bounds__(256, 1) void ttt_persistent(float* __restrict__ out,
                                                         int nb)
{
    __shared__ __align__(16) float SM[4 * STG_FL];
    const unsigned smu = (unsigned)__cvta_generic_to_shared(SM);
    const int bid = blockIdx.x, tid = threadIdx.x;
    const int w = tid >> 5, lane = tid & 31;
    const int wm = w >> 2, wn = w & 3;
    const int g = lane >> 2, q = lane & 3;
    const int gw = (bid * 256 + tid) >> 5;

    for (int i = 0; i <= T_; i++) {
        // ---- P1: h2(i-1) + a,h(i). Full-K 32x64 tiles, fused bias+gelu. ----
        {
            const int nH2 = (i > 0) ? 32 : 0;
            const int nTot = nH2 + ((i < T_) ? 32 : 0);
            for (int u = bid; u < nTot; u += nb) {
                const bool isH2 = (u < nH2);
                const int v = isH2 ? u : u - nH2;
                int m0 = (v & 7) * 32, n0 = (v >> 3) * 64;
                float acc[1][2][4] = {};
                if (isH2) {
                    const float* Qp = g_Q + (size_t)(i - 1) * NH;
                    tile_cp<0, 32, 1>(Qp, g_W1, SM, smu, DD, DD, m0, n0, 0, DD, acc);
                } else {
                    const float* Zp = g_Z + (size_t)i * NH;
                    tile_cp<0, 32, 0>(Zp, g_W1, SM, smu, DD, DD, m0, n0, 0, DD, acc);
                }
#pragma unroll
                for (int nt = 0; nt < 2; nt++) {
                    int m = m0 + wm * 16 + g;
                    int nn = n0 + wn * 16 + nt * 8 + q * 2;
                    float2 bb = *(const float2*)(g_b1 + nn);
                    float s0 = acc[0][nt][0] + bb.x, s1 = acc[0][nt][1] + bb.y;
                    float s2 = acc[0][nt][2] + bb.x, s3 = acc[0][nt][3] + bb.y;
                    if (isH2) {
                        *(float2*)(g_h2 + (size_t)m * H4 + nn) =
                            make_float2(gelu_f(s0), gelu_f(s1));
                        *(float2*)(g_h2 + (size_t)(m + 8) * H4 + nn) =
                            make_float2(gelu_f(s2), gelu_f(s3));
                    } else {
                        *(float2*)(g_a + (size_t)m * H4 + nn) = make_float2(s0, s1);
                        *(float2*)(g_h + (size_t)m * H4 + nn) =
                            make_float2(gelu_f(s0), gelu_f(s1));
                        *(float2*)(g_a + (size_t)(m + 8) * H4 + nn) = make_float2(s2, s3);
                        *(float2*)(g_h + (size_t)(m + 8) * H4 + nn) =
                            make_float2(gelu_f(s2), gelu_f(s3));
                    }
                }
            }
        }
        grid_sync(nb);

        // ---- P2: out(i-1) + dr(i). K=256 32x64 tiles. ----
        {
            const int nOut = (i > 0) ? 128 : 0;
            const int nTot = nOut + ((i < T_) ? 128 : 0);
            for (int u = bid; u < nTot; u += nb) {
                const bool isOut = (u < nOut);
                const int v = isOut ? u : u - nOut;
                int m0 = (v & 7) * 32, n0 = (v >> 3) * 64;
                float acc[1][2][4] = {};
                if (isOut) {
                    tile_cp<0, 32, 1>(g_h2, g_W2, SM, smu, H4, H4, m0, n0, 0, H4, acc);
                    const float* Qp = g_Q + (size_t)(i - 1) * NH;
                    float* od = out + (size_t)(i - 1) * NH;
#pragma unroll
                    for (int nt = 0; nt < 2; nt++) {
                        int m = m0 + wm * 16 + g;
                        int nn = n0 + wn * 16 + nt * 8 + q * 2;
                        float2 bb = *(const float2*)(g_b2 + nn);
                        {
                            float2 qv = *(const float2*)(Qp + (size_t)m * HH + nn);
                            *(float2*)(od + (size_t)m * HH + nn) = make_float2(
                                qv.x + acc[0][nt][0] + bb.x,
                                qv.y + acc[0][nt][1] + bb.y);
                        }
                        {
                            int m8 = m + 8;
                            float2 qv = *(const float2*)(Qp + (size_t)m8 * HH + nn);
                            *(float2*)(od + (size_t)m8 * HH + nn) = make_float2(
                                qv.x + acc[0][nt][2] + bb.x,
                                qv.y + acc[0][nt][3] + bb.y);
                        }
                    }
                } else {
                    tile_cp<0, 32, 0>(g_h, g_W2, SM, smu, H4, H4, m0, n0, 0, H4, acc);
                    const float* Zp = g_Z + (size_t)i * NH;
                    const float* Yp = g_Y + (size_t)i * NH;
#pragma unroll
                    for (int nt = 0; nt < 2; nt++) {
                        int m = m0 + wm * 16 + g;
                        int nn = n0 + wn * 16 + nt * 8 + q * 2;
                        float2 bb = *(const float2*)(g_b2 + nn);
                        {
                            float2 zz = *(const float2*)(Zp + (size_t)m * HH + nn);
                            float2 yy = *(const float2*)(Yp + (size_t)m * HH + nn);
                            *(float2*)(g_dr + (size_t)m * HH + nn) = make_float2(
                                C2 * (zz.x + acc[0][nt][0] + bb.x - yy.x),
                                C2 * (zz.y + acc[0][nt][1] + bb.y - yy.y));
                        }
                        {
                            int m8 = m + 8;
                            float2 zz = *(const float2*)(Zp + (size_t)m8 * HH + nn);
                            float2 yy = *(const float2*)(Yp + (size_t)m8 * HH + nn);
                            *(float2*)(g_dr + (size_t)m8 * HH + nn) = make_float2(
                                C2 * (zz.x + acc[0][nt][2] + bb.x - yy.x),
                                C2 * (zz.y + acc[0][nt][3] + bb.y - yy.y));
                        }
                    }
                }
            }
        }
        grid_sync(nb);
        if (i == T_) break;

        const float* Zt = g_Z + (size_t)i * NH;

        // ---- P3: da = (dr @ W2) * gelu'(a). Full-K NN, fused epilogue. ----
        for (int u = bid; u < 32; u += nb) {
            int m0 = (u & 7) * 32, n0 = (u >> 3) * 64;
            float acc[1][2][4] = {};
            tile_cp<1, 32, 0>(g_dr, g_W2, SM, smu, HH, H4, m0, n0, 0, HH, acc);
#pragma unroll
            for (int nt = 0; nt < 2; nt++) {
                int m = m0 + wm * 16 + g;
                int nn = n0 + wn * 16 + nt * 8 + q * 2;
                {
                    float2 av = *(const float2*)(g_a + (size_t)m * H4 + nn);
                    *(float2*)(g_da + (size_t)m * H4 + nn) = make_float2(
                        acc[0][nt][0] * gelu_grad(av.x),
                        acc[0][nt][1] * gelu_grad(av.y));
                }
                {
                    int m8 = m + 8;
                    float2 av = *(const float2*)(g_a + (size_t)m8 * H4 + nn);
                    *(float2*)(g_da + (size_t)m8 * H4 + nn) = make_float2(
                        acc[0][nt][2] * gelu_grad(av.x),
                        acc[0][nt][3] * gelu_grad(av.y));
                }
            }
        }
        grid_sync(nb);

        // ---- P4: weight updates (tf32 TN 64x64, Kn=256) + biases ----
        for (int u = bid; u < 128; u += nb) {
            if (u < 64) {
                int i0 = (u & 15) * 64, j0 = (u >> 4) * 64;
                float acc[2][2][4] = {};
                tile_cp<2, 64, 0>(g_dr, g_h, SM, smu, HH, H4, i0, j0, 0, NB, acc);
#pragma unroll
                for (int mt = 0; mt < 2; mt++)
#pragma unroll
                    for (int nt = 0; nt < 2; nt++) {
                        int ii = i0 + wm * 32 + mt * 16 + g;
                        int j = j0 + wn * 16 + nt * 8 + q * 2;
                        float2* p0 = (float2*)(g_W2 + (size_t)ii * H4 + j);
                        float2 o0 = *p0;
                        o0.x -= LR * acc[mt][nt][0]; o0.y -= LR * acc[mt][nt][1];
                        *p0 = o0;
                        float2* p1 = (float2*)(g_W2 + (size_t)(ii + 8) * H4 + j);
                        float2 o1 = *p1;
                        o1.x -= LR * acc[mt][nt][2]; o1.y -= LR * acc[mt][nt][3];
                        *p1 = o1;
                    }
            } else {
                int v = u - 64;
                int j0 = (v & 3) * 64, i0 = (v >> 2) * 64;
                float acc[2][2][4] = {};
                tile_cp<2, 64, 0>(g_da, Zt, SM, smu, H4, DD, j0, i0, 0, NB, acc);
#pragma unroll
                for (int mt = 0; mt < 2; mt++)
#pragma unroll
                    for (int nt = 0; nt < 2; nt++) {
                        int j = j0 + wm * 32 + mt * 16 + g;
                        int ii = i0 + wn * 16 + nt * 8 + q * 2;
                        float2* p0 = (float2*)(g_W1 + (size_t)j * DD + ii);
                        float2 o0 = *p0;
                        o0.x -= LR * acc[mt][nt][0]; o0.y -= LR * acc[mt][nt][1];
                        *p0 = o0;
                        float2* p1 = (float2*)(g_W1 + (size_t)(j + 8) * DD + ii);
                        float2 o1 = *p1;
                        o1.x -= LR * acc[mt][nt][2]; o1.y -= LR * acc[mt][nt][3];
                        *p1 = o1;
                    }
            }
        }
        // bias colsums (warp-parallel, no intra-block syncs)
        for (int c = gw; c < HH; c += nb * 8) {
            float s = 0.f;
            for (int n = lane; n < NB; n += 32) s += g_dr[(size_t)n * HH + c];
#pragma unroll
            for (int o = 16; o > 0; o >>= 1) s += __shfl_xor_sync(0xffffffffu, s, o);
            if (lane == 0) g_b2[c] -= LR * s;
        }
        for (int c = gw; c < H4; c += nb * 8) {
            float s = 0.f;
            for (int n = lane; n < NB; n += 32) s += g_da[(size_t)n * H4 + c];
#pragma unroll
            for (int o = 16; o > 0; o >>= 1) s += __shfl_xor_sync(0xffffffffu, s, o);
            if (lane == 0) g_b1[c] -= LR * s;
        }
        grid_sync(nb);
    }
}

// ---------------------------------------------------------------------------
// kernel_launch
// ---------------------------------------------------------------------------
extern "C" void kernel_launch(void* const* d_in, const int* in_sizes, int n_in,
                              void* d_out, int out_size)
{
    (void)in_sizes; (void)n_in; (void)out_size;
    const float* in_seq = (const float*)d_in[0];
    const float* t_k = (const float*)d_in[1];
    const float* t_v = (const float*)d_in[2];
    const float* t_q = (const float*)d_in[3];

    float *Z, *Y, *Q, *W1, *b1, *W2, *b2;
    cudaGetSymbolAddress((void**)&Z, g_Z);
    cudaGetSymbolAddress((void**)&Y, g_Y);
    cudaGetSymbolAddress((void**)&Q, g_Q);
    cudaGetSymbolAddress((void**)&W1, g_W1);
    cudaGetSymbolAddress((void**)&b1, g_b1);
    cudaGetSymbolAddress((void**)&W2, g_W2);
    cudaGetSymbolAddress((void**)&b2, g_b2);

    cudaMemcpyAsync(W1, d_in[4], sizeof(float) * H4 * HH, cudaMemcpyDeviceToDevice, 0);
    cudaMemcpyAsync(b1, d_in[5], sizeof(float) * H4, cudaMemcpyDeviceToDevice, 0);
    cudaMemcpyAsync(W2, d_in[6], sizeof(float) * HH * H4, cudaMemcpyDeviceToDevice, 0);
    cudaMemcpyAsync(b2, d_in[7], sizeof(float) * HH, cudaMemcpyDeviceToDevice, 0);

    // Phase A: tf32 tensor-core GEMMs
    const int M_big = T_ * NB;
    dim3 gA(M_big / 128, HH / 128);
    gemm_nt_tf32<<<gA, 256>>>(in_seq, t_k, Z, M_big, HH, DD);
    gemm_nt_tf32<<<gA, 256>>>(in_seq, t_v, Y, M_big, HH, DD);
    gemm_nt_tf32<<<gA, 256>>>(in_seq, t_q, Q, M_big, HH, DD);

    // Phase B: one persistent kernel, exactly one block per SM.
    int sms = 0;
    cudaDeviceGetAttribute(&sms, cudaDevAttrMultiProcessorCount, 0);
    if (sms <= 0 || sms > 148) sms = 148;
    ttt_persistent<<<sms, 256>>>((float*)d_out, sms);
}